// round 10
// baseline (speedup 1.0000x reference)
#include <cuda_runtime.h>
#include <cstdint>

#define T_LEN 1024
#define B_SZ  512
#define D_IN  46
#define H_SZ  128
#define G3    384   // 3*H

#define KC_REG  5
#define KC_SMEM 3

// Smem float offsets (single fused kernel)
#define WS4_F4_STRIDE 1154                  // 9*128 + 2 pad float4 per kq
#define OFF_HS   (WS4_F4_STRIDE * 4 * 4)    // 18464 floats
#define HS_BSTR  144                        // per-batch stride: 4 segs x 36
#define HS_BUF   576
#define OFF_WIH  (OFF_HS + 2 * HS_BUF)      // 19616 (byte-16 aligned)
#define WIH_STR  52                         // row pad: u*52 mod 32 banks all-distinct
#define OFF_HB   (OFF_WIH + 384 * WIH_STR)  // 39584 (byte-16 aligned)
#define HB_BSTR  52                         // hist row pad: kq*52 mod 32 distinct
#define HB_BUF   (4 * HB_BSTR)              // 208
#define SMEM_F   (OFF_HB + 2 * HB_BUF)      // 40000 floats = 160000 B

#define FMA2(acc, a, b) asm("fma.rn.f32x2 %0, %1, %2, %0;" : "+l"(acc) : "l"(a), "l"(b))

__device__ __forceinline__ float pair_sum(unsigned long long v) {
    float lo, hi;
    asm("mov.b64 {%0,%1}, %2;" : "=f"(lo), "=f"(hi) : "l"(v));
    return lo + hi;
}

// ---------------------------------------------------------------------------
// Fused GRU: 128 CTAs x 4 batches, 512 threads.
// Thread (kq = lane>>3, u = warp*8 + lane&7) owns gate rows u,128+u,256+u:
//   - recurrent partial dots over K-quarter kq (regs + smem W_hh)
//   - butterfly (^8,^16) cross-kq reduction; replica kq combines batch kq
//   - computes its OWN x_proj[t+1] 3-vector in registers from hist (smem)
// One barrier per step; h double-buffered; hist rows double-buffered cp.async.
// ---------------------------------------------------------------------------
__global__ __launch_bounds__(512, 1) void gru_fused_kernel(const float* __restrict__ hist,
                                                           const float* __restrict__ W_ih,
                                                           const float* __restrict__ W_hh,
                                                           const float* __restrict__ b_ih,
                                                           const float* __restrict__ b_hh,
                                                           const float* __restrict__ h0,
                                                           float* __restrict__ out) {
    extern __shared__ float smem[];
    float4* Ws4 = (float4*)smem;
    float*  h_s = smem + OFF_HS;
    float*  wih = smem + OFF_WIH;
    float*  hb  = smem + OFF_HB;

    const int t    = threadIdx.x;
    const int w    = t >> 5;
    const int lane = t & 31;
    const int kq   = lane >> 3;           // K-quarter; also the batch this thread combines
    const int u    = w * 8 + (lane & 7);  // hidden index 0..127
    const int b0   = blockIdx.x * 4;

    // ---- W_hh: 5 chunks/row in regs, 3 in smem (R9 layout, unchanged) ----
    unsigned long long Wr[3][2 * KC_REG];
#pragma unroll
    for (int j = 0; j < 3; j++)
#pragma unroll
        for (int p = 0; p < 2 * KC_REG; p++)
            Wr[j][p] = *(const unsigned long long*)(W_hh + (size_t)(j * H_SZ + u) * H_SZ +
                                                    32 * kq + 2 * p);
    for (int idx = t; idx < 4 * 9 * 128; idx += 512) {
        const int kqq = idx / 1152;
        const int within = idx - kqq * 1152;
        const int uu = within & 127;
        const int q = within >> 7;
        const int kr = q / 3, j = q - 3 * kr;
        Ws4[kqq * WS4_F4_STRIDE + within] =
            *(const float4*)(W_hh + (size_t)(j * H_SZ + uu) * H_SZ +
                             32 * kqq + (KC_REG + kr) * 4);
    }
    // ---- W_ih into smem, rows padded to 52 (cols 46..51 zero) ----
    for (int idx = t; idx < 384 * WIH_STR; idx += 512) {
        const int g = idx / WIH_STR, c = idx - g * WIH_STR;
        wih[idx] = (c < D_IN) ? W_ih[(size_t)g * D_IN + c] : 0.f;
    }
    // ---- hist buffers: zero pads, then stage rows t=0 and t=1 ----
    for (int i = t; i < 2 * HB_BUF; i += 512) hb[i] = 0.f;
    // h buffer 0
    for (int i = t; i < 4 * H_SZ; i += 512) {
        const int b = i >> 7, g = i & 127;
        h_s[b * HS_BSTR + (g >> 5) * 36 + (g & 31)] = h0[g];
    }
    float bh[3], bi[3];
#pragma unroll
    for (int j = 0; j < 3; j++) { bh[j] = b_hh[j * H_SZ + u]; bi[j] = b_ih[j * H_SZ + u]; }

    __syncthreads();  // pads zeroed before cp.async partial-row writes

    // Stage hist rows 0 and 1 (8B cp.async; rows are 8B-aligned: 46*4=184)
    if (t < 184) {
        const int buf = t / 92, within = t - buf * 92;
        const int pb = within / 23, c = within - pb * 23;
        const unsigned saddr = (unsigned)__cvta_generic_to_shared(
            hb + buf * HB_BUF + pb * HB_BSTR + 2 * c);
        const float* src = hist + ((size_t)(b0 + pb) * T_LEN + buf) * D_IN + 2 * c;
        asm volatile("cp.async.ca.shared.global [%0], [%1], 8;" :: "r"(saddr), "l"(src));
    }
    asm volatile("cp.async.commit_group;");
    asm volatile("cp.async.wait_group 0;");
    __syncthreads();

    // x_proj for step 0 (from hb[0]) into registers.
    float xc[3];
    {
        const ulonglong2* xh = (const ulonglong2*)(hb + kq * HB_BSTR);
#pragma unroll
        for (int j = 0; j < 3; j++) {
            const ulonglong2* wr = (const ulonglong2*)(wih + (j * H_SZ + u) * WIH_STR);
            unsigned long long a = 0ull;
#pragma unroll
            for (int i = 0; i < 12; i++) {
                const ulonglong2 xv = xh[i];
                const ulonglong2 wv = wr[i];
                FMA2(a, wv.x, xv.x);
                FMA2(a, wv.y, xv.y);
            }
            xc[j] = pair_sum(a) + bi[j];
        }
    }

    const float4* wsb = Ws4 + (size_t)kq * WS4_F4_STRIDE;
    float hnew = 0.f;

    for (int step = 0; step < T_LEN; step++) {
        const int cur = step & 1, nxt = cur ^ 1;
        asm volatile("cp.async.wait_group 0;");
        __syncthreads();  // hist[step+1] in hb[nxt]; h_s[cur] from prev combine visible

        // Prefetch hist row step+2 into hb[cur] (its row `step` is consumed).
        if (step + 2 < T_LEN) {
            if (t < 92) {
                const int pb = t / 23, c = t - pb * 23;
                const unsigned saddr = (unsigned)__cvta_generic_to_shared(
                    hb + cur * HB_BUF + pb * HB_BSTR + 2 * c);
                const float* src =
                    hist + ((size_t)(b0 + pb) * T_LEN + step + 2) * D_IN + 2 * c;
                asm volatile("cp.async.ca.shared.global [%0], [%1], 8;"
                             :: "r"(saddr), "l"(src));
            }
        }
        asm volatile("cp.async.commit_group;");

        // ---- recurrent partial dots over K-quarter kq ----
        unsigned long long acc[3][4];
#pragma unroll
        for (int j = 0; j < 3; j++)
#pragma unroll
            for (int b = 0; b < 4; b++) acc[j][b] = 0ull;

        const float* hsb = h_s + cur * HS_BUF + kq * 36;
#pragma unroll
        for (int kk = 0; kk < KC_REG; kk++) {
#pragma unroll
            for (int b = 0; b < 4; b++) {
                const ulonglong2 hv = *(const ulonglong2*)(hsb + b * HS_BSTR + 4 * kk);
                FMA2(acc[0][b], Wr[0][2 * kk], hv.x); FMA2(acc[0][b], Wr[0][2 * kk + 1], hv.y);
                FMA2(acc[1][b], Wr[1][2 * kk], hv.x); FMA2(acc[1][b], Wr[1][2 * kk + 1], hv.y);
                FMA2(acc[2][b], Wr[2][2 * kk], hv.x); FMA2(acc[2][b], Wr[2][2 * kk + 1], hv.y);
            }
        }
#pragma unroll
        for (int kr = 0; kr < KC_SMEM; kr++) {
            const ulonglong2 w0 = *(const ulonglong2*)(wsb + (kr * 3 + 0) * 128 + u);
            const ulonglong2 w1 = *(const ulonglong2*)(wsb + (kr * 3 + 1) * 128 + u);
            const ulonglong2 w2 = *(const ulonglong2*)(wsb + (kr * 3 + 2) * 128 + u);
#pragma unroll
            for (int b = 0; b < 4; b++) {
                const ulonglong2 hv =
                    *(const ulonglong2*)(hsb + b * HS_BSTR + 4 * (KC_REG + kr));
                FMA2(acc[0][b], w0.x, hv.x); FMA2(acc[0][b], w0.y, hv.y);
                FMA2(acc[1][b], w1.x, hv.x); FMA2(acc[1][b], w1.y, hv.y);
                FMA2(acc[2][b], w2.x, hv.x); FMA2(acc[2][b], w2.y, hv.y);
            }
        }

        // ---- fused x_proj for step+1 (independent of h; fills idle slots) ----
        float xn3[3];
        if (step + 1 < T_LEN) {
            const ulonglong2* xh = (const ulonglong2*)(hb + nxt * HB_BUF + kq * HB_BSTR);
#pragma unroll
            for (int j = 0; j < 3; j++) {
                const ulonglong2* wr = (const ulonglong2*)(wih + (j * H_SZ + u) * WIH_STR);
                unsigned long long a = 0ull;
#pragma unroll
                for (int i = 0; i < 12; i++) {
                    const ulonglong2 xv = xh[i];
                    const ulonglong2 wv = wr[i];
                    FMA2(a, wv.x, xv.x);
                    FMA2(a, wv.y, xv.y);
                }
                xn3[j] = pair_sum(a) + bi[j];
            }
        }

        // ---- cross-kq butterfly reduction; replica kq keeps batch kq ----
        float gh[3];
#pragma unroll
        for (int j = 0; j < 3; j++) {
            float keep = 0.f;
#pragma unroll
            for (int b = 0; b < 4; b++) {
                float s = pair_sum(acc[j][b]);
                s += __shfl_xor_sync(0xffffffffu, s, 8);
                s += __shfl_xor_sync(0xffffffffu, s, 16);
                if (b == kq) keep = s;
            }
            gh[j] = keep + bh[j];
        }

        // ---- combine for (batch kq, hidden u); write NEXT h buffer ----
        {
            const float hprev = h_s[cur * HS_BUF + kq * HS_BSTR + (u >> 5) * 36 + (u & 31)];
            const float rr = __fdividef(1.f, 1.f + __expf(-(xc[0] + gh[0])));
            const float zz = __fdividef(1.f, 1.f + __expf(-(xc[1] + gh[1])));
            const float pre = xc[2] + rr * gh[2];
            // tanh(x) = 1 - 2/(exp(2x)+1); saturates correctly
            const float nn = 1.f - 2.f * __fdividef(1.f, 1.f + __expf(2.f * pre));
            hnew = nn + zz * (hprev - nn);
            h_s[nxt * HS_BUF + kq * HS_BSTR + (u >> 5) * 36 + (u & 31)] = hnew;
        }
        if (step + 1 < T_LEN) { xc[0] = xn3[0]; xc[1] = xn3[1]; xc[2] = xn3[2]; }
    }

    out[(size_t)(b0 + kq) * H_SZ + u] = hnew;
}

extern "C" void kernel_launch(void* const* d_in, const int* in_sizes, int n_in,
                              void* d_out, int out_size) {
    const float* hist = (const float*)d_in[0];  // [512,1024,46]
    const float* W_ih = (const float*)d_in[1];  // [384,46]
    const float* W_hh = (const float*)d_in[2];  // [384,128]
    const float* b_ih = (const float*)d_in[3];  // [384]
    const float* b_hh = (const float*)d_in[4];  // [384]
    const float* h0   = (const float*)d_in[5];  // [1,1,128]
    float* out = (float*)d_out;                 // [512,128]

    const int SMEM = SMEM_F * 4;  // 160000 B
    cudaFuncSetAttribute(gru_fused_kernel,
                         cudaFuncAttributeMaxDynamicSharedMemorySize, SMEM);

    gru_fused_kernel<<<B_SZ / 4, 512, SMEM>>>(hist, W_ih, W_hh, b_ih, b_hh, h0, out);
}

// round 11
// speedup vs baseline: 1.7305x; 1.7305x over previous
#include <cuda_runtime.h>
#include <cstdint>

#define T_LEN 1024
#define B_SZ  512
#define D_IN  46
#define H_SZ  128
#define G3    384   // 3*H

#define KC_REG  5
#define KC_SMEM 3

#define WS4_F4_STRIDE 1154
#define OFF_HS   (WS4_F4_STRIDE * 4 * 4)   // 18464 floats
#define HS_BSTR  144
#define HS_BUF   576
#define OFF_XP   (OFF_HS + 2 * HS_BUF)     // 19616
#define XP_BSTR  392
#define XP_BUF   (4 * XP_BSTR)             // 1568
#define SMEM_F   (OFF_XP + 2 * XP_BUF)     // 22752 floats = 91008 B

#define FMA2(acc, a, b) asm("fma.rn.f32x2 %0, %1, %2, %0;" : "+l"(acc) : "l"(a), "l"(b))

__device__ __forceinline__ float pair_sum(unsigned long long v) {
    float lo, hi;
    asm("mov.b64 {%0,%1}, %2;" : "=f"(lo), "=f"(hi) : "l"(v));
    return lo + hi;
}

static __device__ float g_xproj[(size_t)T_LEN * B_SZ * G3];

// ---------------------------------------------------------------------------
// Kernel 1 (v3): x_proj. 192 threads, 2 gates/thread, and now 2 independent
// accumulator chains per gate (even/odd K-chunks) -> 4 FFMA2 chains per
// thread so 3 warps/SMSP can saturate the fma pipe (2 chains was 1.5/2.0).
// ---------------------------------------------------------------------------
__global__ __launch_bounds__(192, 2) void xproj_kernel(const float* __restrict__ hist,
                                                       const float* __restrict__ W_ih,
                                                       const float* __restrict__ b_ih) {
    __shared__ float xs[128 * 48];
    const int tid = threadIdx.x;
    const int m_base = blockIdx.x * 128;

    {
        const float2* src = (const float2*)(hist + (size_t)m_base * D_IN);
        for (int i = tid; i < 128 * 23; i += 192) {
            const int row = i / 23, c = i - row * 23;
            *(float2*)(xs + row * 48 + 2 * c) = src[i];
        }
    }

    unsigned long long w0[23], w1[23];
#pragma unroll
    for (int k = 0; k < 23; k++) {
        w0[k] = *(const unsigned long long*)(W_ih + (size_t)tid * D_IN + 2 * k);
        w1[k] = *(const unsigned long long*)(W_ih + (size_t)(tid + 192) * D_IN + 2 * k);
    }
    const float bias0 = b_ih[tid];
    const float bias1 = b_ih[tid + 192];
    __syncthreads();

#pragma unroll 2
    for (int m = 0; m < 128; m++) {
        const ulonglong2* xr = (const ulonglong2*)(xs + m * 48);
        // 4 independent chains: {gate0, gate1} x {even chunk, odd chunk}
        unsigned long long a0e = 0ull, a0o = 0ull, a1e = 0ull, a1o = 0ull;
#pragma unroll
        for (int i = 0; i < 12; i += 2) {
            const ulonglong2 xe = xr[i];
            const ulonglong2 xo = xr[i + 1];
            FMA2(a0e, w0[2 * i], xe.x);
            FMA2(a1e, w1[2 * i], xe.x);
            FMA2(a0e, w0[2 * i + 1], xe.y);
            FMA2(a1e, w1[2 * i + 1], xe.y);
            FMA2(a0o, w0[2 * i + 2], xo.x);
            FMA2(a1o, w1[2 * i + 2], xo.x);
            if (2 * i + 3 < 23) {
                FMA2(a0o, w0[2 * i + 3], xo.y);
                FMA2(a1o, w1[2 * i + 3], xo.y);
            }
        }
        const int mm = m_base + m;
        const int b = mm >> 10, t = mm & 1023;
        float* dst = g_xproj + ((size_t)t * B_SZ + b) * G3;
        dst[tid]       = pair_sum(a0e) + pair_sum(a0o) + bias0;
        dst[tid + 192] = pair_sum(a1e) + pair_sum(a1o) + bias1;
    }
}

// ---------------------------------------------------------------------------
// Kernel 2: GRU scan — identical to R9 (proven 1605 us).
// ---------------------------------------------------------------------------
__global__ __launch_bounds__(512, 1) void gru_scan_kernel(const float* __restrict__ W_hh,
                                                          const float* __restrict__ b_hh,
                                                          const float* __restrict__ h0,
                                                          float* __restrict__ out) {
    extern __shared__ float smem[];
    float4* Ws4 = (float4*)smem;
    float*  h_s = smem + OFF_HS;
    float*  xp  = smem + OFF_XP;

    const int t    = threadIdx.x;
    const int w    = t >> 5;
    const int lane = t & 31;
    const int kq   = lane >> 3;           // K-quarter; also the batch this thread combines
    const int u    = w * 8 + (lane & 7);  // hidden index 0..127

    unsigned long long Wr[3][2 * KC_REG];
#pragma unroll
    for (int j = 0; j < 3; j++)
#pragma unroll
        for (int p = 0; p < 2 * KC_REG; p++)
            Wr[j][p] = *(const unsigned long long*)(W_hh + (size_t)(j * H_SZ + u) * H_SZ +
                                                    32 * kq + 2 * p);

    for (int idx = t; idx < 4 * 9 * 128; idx += 512) {
        const int kqq = idx / 1152;
        const int within = idx - kqq * 1152;
        const int uu = within & 127;
        const int q = within >> 7;
        const int kr = q / 3, j = q - 3 * kr;
        Ws4[kqq * WS4_F4_STRIDE + within] =
            *(const float4*)(W_hh + (size_t)(j * H_SZ + uu) * H_SZ +
                             32 * kqq + (KC_REG + kr) * 4);
    }
    for (int i = t; i < 4 * H_SZ; i += 512) {
        const int b = i >> 7, g = i & 127;
        h_s[b * HS_BSTR + (g >> 5) * 36 + (g & 31)] = h0[g];
    }
    float bh[3];
#pragma unroll
    for (int j = 0; j < 3; j++) bh[j] = b_hh[j * H_SZ + u];

    const int b0 = blockIdx.x * 4;
    if (t < 384) {
        const int pb = t / 96, off = (t - pb * 96) * 4;
        const unsigned saddr =
            (unsigned)__cvta_generic_to_shared(xp + pb * XP_BSTR + off);
        const float* src = g_xproj + ((size_t)0 * B_SZ + b0 + pb) * G3 + off;
        asm volatile("cp.async.cg.shared.global [%0], [%1], 16;" :: "r"(saddr), "l"(src));
    }
    asm volatile("cp.async.commit_group;");

    const float4* wsb = Ws4 + (size_t)kq * WS4_F4_STRIDE;
    float hnew = 0.f;

    for (int step = 0; step < T_LEN; step++) {
        const int cur = step & 1, nxt = cur ^ 1;
        asm volatile("cp.async.wait_group 0;");
        __syncthreads();  // xp[cur] landed; h_s[cur] (prev combine) visible

        if (step + 1 < T_LEN) {
            if (t < 384) {
                const int pb = t / 96, off = (t - pb * 96) * 4;
                const unsigned saddr = (unsigned)__cvta_generic_to_shared(
                    xp + nxt * XP_BUF + pb * XP_BSTR + off);
                const float* src =
                    g_xproj + ((size_t)(step + 1) * B_SZ + b0 + pb) * G3 + off;
                asm volatile("cp.async.cg.shared.global [%0], [%1], 16;"
                             :: "r"(saddr), "l"(src));
            }
            asm volatile("cp.async.commit_group;");
        }

        unsigned long long acc[3][4];
#pragma unroll
        for (int j = 0; j < 3; j++)
#pragma unroll
            for (int b = 0; b < 4; b++) acc[j][b] = 0ull;

        const float* hb = h_s + cur * HS_BUF + kq * 36;
#pragma unroll
        for (int kk = 0; kk < KC_REG; kk++) {
#pragma unroll
            for (int b = 0; b < 4; b++) {
                const ulonglong2 hv = *(const ulonglong2*)(hb + b * HS_BSTR + 4 * kk);
                FMA2(acc[0][b], Wr[0][2 * kk], hv.x); FMA2(acc[0][b], Wr[0][2 * kk + 1], hv.y);
                FMA2(acc[1][b], Wr[1][2 * kk], hv.x); FMA2(acc[1][b], Wr[1][2 * kk + 1], hv.y);
                FMA2(acc[2][b], Wr[2][2 * kk], hv.x); FMA2(acc[2][b], Wr[2][2 * kk + 1], hv.y);
            }
        }
#pragma unroll
        for (int kr = 0; kr < KC_SMEM; kr++) {
            const ulonglong2 w0 = *(const ulonglong2*)(wsb + (kr * 3 + 0) * 128 + u);
            const ulonglong2 w1 = *(const ulonglong2*)(wsb + (kr * 3 + 1) * 128 + u);
            const ulonglong2 w2 = *(const ulonglong2*)(wsb + (kr * 3 + 2) * 128 + u);
#pragma unroll
            for (int b = 0; b < 4; b++) {
                const ulonglong2 hv =
                    *(const ulonglong2*)(hb + b * HS_BSTR + 4 * (KC_REG + kr));
                FMA2(acc[0][b], w0.x, hv.x); FMA2(acc[0][b], w0.y, hv.y);
                FMA2(acc[1][b], w1.x, hv.x); FMA2(acc[1][b], w1.y, hv.y);
                FMA2(acc[2][b], w2.x, hv.x); FMA2(acc[2][b], w2.y, hv.y);
            }
        }

        // Cross-kq reduction per (gate j, batch b): butterfly ^8, ^16.
        float gh[3];
#pragma unroll
        for (int j = 0; j < 3; j++) {
            float keep = 0.f;
#pragma unroll
            for (int b = 0; b < 4; b++) {
                float s = pair_sum(acc[j][b]);
                s += __shfl_xor_sync(0xffffffffu, s, 8);
                s += __shfl_xor_sync(0xffffffffu, s, 16);
                if (b == kq) keep = s;
            }
            gh[j] = keep + bh[j];
        }

        // Combine for (batch kq, hidden u); write into NEXT h buffer.
        {
            const float* xb = xp + cur * XP_BUF + kq * XP_BSTR;
            const float xr = xb[u];
            const float xz = xb[H_SZ + u];
            const float xn = xb[2 * H_SZ + u];
            const float hprev = h_s[cur * HS_BUF + kq * HS_BSTR + (u >> 5) * 36 + (u & 31)];
            const float rr = __fdividef(1.f, 1.f + __expf(-(xr + gh[0])));
            const float zz = __fdividef(1.f, 1.f + __expf(-(xz + gh[1])));
            const float pre = xn + rr * gh[2];
            // tanh(x) = 1 - 2/(exp(2x)+1); saturates correctly
            const float nn = 1.f - 2.f * __fdividef(1.f, 1.f + __expf(2.f * pre));
            hnew = nn + zz * (hprev - nn);
            h_s[nxt * HS_BUF + kq * HS_BSTR + (u >> 5) * 36 + (u & 31)] = hnew;
        }
    }

    out[(size_t)(b0 + kq) * H_SZ + u] = hnew;
}

extern "C" void kernel_launch(void* const* d_in, const int* in_sizes, int n_in,
                              void* d_out, int out_size) {
    const float* hist = (const float*)d_in[0];  // [512,1024,46]
    const float* W_ih = (const float*)d_in[1];  // [384,46]
    const float* W_hh = (const float*)d_in[2];  // [384,128]
    const float* b_ih = (const float*)d_in[3];  // [384]
    const float* b_hh = (const float*)d_in[4];  // [384]
    const float* h0   = (const float*)d_in[5];  // [1,1,128]
    float* out = (float*)d_out;                 // [512,128]

    const int SMEM_SCAN = SMEM_F * 4;  // 91008 B
    cudaFuncSetAttribute(gru_scan_kernel,
                         cudaFuncAttributeMaxDynamicSharedMemorySize, SMEM_SCAN);

    xproj_kernel<<<(B_SZ * T_LEN) / 128, 192>>>(hist, W_ih, b_ih);
    gru_scan_kernel<<<B_SZ / 4, 512, SMEM_SCAN>>>(W_hh, b_hh, h0, out);
}